// round 6
// baseline (speedup 1.0000x reference)
#include <cuda_runtime.h>
#include <cstdint>

#define H  16
#define S  4096
#define DH 128
#define DM 2048
#define BM 64
#define BN 64
#define NT 256            // 8 warps

#define SROW 136          // Q/K/P row stride (floats), conflict-free LDS.64
#define VSTR 72           // V row stride (floats), 64 kv cols + pad

// float offsets within dynamic SMEM
#define F_Q   0
#define F_KP  (F_Q + BM*SROW)       // K tile (packed), later P tile (packed)
#define F_V   (F_KP + BN*SROW)      // V: [d=128][kv=64] packed pairs
#define F_X1  (F_V + DH*VSTR)       // rowmax exchange: 64 rows x 4 warps
#define F_X2  (F_X1 + 256)          // rowsum exchange
#define SMEM_FLOATS (F_X2 + 256)
#define SMEM_BYTES  (SMEM_FLOATS * 4)   // 108,544 B -> 2 CTAs/SM

// Prepass scratch: tf32-rounded, pair-packed tensors
// Qp/Kp: [head][row][128], each 8-col block permuted (x0,x4,x1,x5,x2,x6,x3,x7)
// Vp:    [head][T=64 kv-tiles][d=128][64] pairs over kv, same permute
__device__ float g_Qs[H * S * DH];
__device__ float g_Ks[H * S * DH];
__device__ float g_Vs[H * S * DH];

__device__ __forceinline__ float tfr(float f){
    uint32_t r; asm("cvt.rna.tf32.f32 %0, %1;" : "=r"(r) : "f"(f));
    return __uint_as_float(r);
}
__device__ __forceinline__ float ex2f(float x){
    float r; asm("ex2.approx.ftz.f32 %0, %1;" : "=f"(r) : "f"(x)); return r;
}
__device__ __forceinline__ void mma_tf32(float c[4],
    float a0, float a1, float a2, float a3, float b0, float b1)
{
    asm volatile(
        "mma.sync.aligned.m16n8k8.row.col.f32.tf32.tf32.f32 "
        "{%0,%1,%2,%3}, {%4,%5,%6,%7}, {%8,%9}, {%0,%1,%2,%3};\n"
        : "+f"(c[0]), "+f"(c[1]), "+f"(c[2]), "+f"(c[3])
        : "r"(__float_as_uint(a0)), "r"(__float_as_uint(a1)),
          "r"(__float_as_uint(a2)), "r"(__float_as_uint(a3)),
          "r"(__float_as_uint(b0)), "r"(__float_as_uint(b1)));
}
__device__ __forceinline__ void cpa16(uint32_t dst, const float* src){
    asm volatile("cp.async.cg.shared.global [%0], [%1], 16;" :: "r"(dst), "l"(src));
}
__device__ __forceinline__ void cpa_commit(){
    asm volatile("cp.async.commit_group;" ::: "memory");
}
__device__ __forceinline__ void cpa_wait0(){
    asm volatile("cp.async.wait_group 0;" ::: "memory");
}

// ---- Prepass 1: Q,K -> tf32, pair-packed rows (Q pre-scaled) ----
__global__ void prep_qk(const float* __restrict__ Q, const float* __restrict__ K)
{
    const float SC = 0.088388347648318447f * 1.4426950408889634f; // 1/sqrt(128)*log2e
    size_t t = (size_t)blockIdx.x * blockDim.x + threadIdx.x;   // H*S*16 threads
    size_t base = t * 8;
    float4 qa = *(const float4*)(Q + base);
    float4 qb = *(const float4*)(Q + base + 4);
    float4 ka = *(const float4*)(K + base);
    float4 kb = *(const float4*)(K + base + 4);
    *(float4*)(g_Qs + base)     = make_float4(tfr(qa.x*SC), tfr(qb.x*SC), tfr(qa.y*SC), tfr(qb.y*SC));
    *(float4*)(g_Qs + base + 4) = make_float4(tfr(qa.z*SC), tfr(qb.z*SC), tfr(qa.w*SC), tfr(qb.w*SC));
    *(float4*)(g_Ks + base)     = make_float4(tfr(ka.x), tfr(kb.x), tfr(ka.y), tfr(kb.y));
    *(float4*)(g_Ks + base + 4) = make_float4(tfr(ka.z), tfr(kb.z), tfr(ka.w), tfr(kb.w));
}

// ---- Prepass 2: V -> tf32, transposed per 64-kv tile, pair-packed over kv ----
__global__ void prep_v(const float* __restrict__ V)
{
    int b    = blockIdx.x;          // 16*64*8 blocks
    int kb   = b & 7;
    int T    = (b >> 3) & 63;
    int head = b >> 9;
    int d    = threadIdx.x;         // 128
    int kv0  = T * 64 + kb * 8;
    const float* src = V + ((size_t)head * S + kv0) * DH + d;
    float x[8];
    #pragma unroll
    for (int w = 0; w < 8; ++w) x[w] = tfr(src[(size_t)w * DH]);
    float* dst = g_Vs + (((size_t)head * 64 + T) * 128 + d) * 64 + kb * 8;
    *(float4*)(dst)     = make_float4(x[0], x[4], x[1], x[5]);
    *(float4*)(dst + 4) = make_float4(x[2], x[6], x[3], x[7]);
}

// ---------------- Main flash-attention kernel ----------------
extern __shared__ float sm[];

__global__ __launch_bounds__(NT, 2)
void fa_kernel(float* __restrict__ Out)
{
    const int qt   = (int)gridDim.x - 1 - (int)blockIdx.x;  // heavy tiles first
    const int head = blockIdx.y;
    const int q0   = qt * BM;
    const int tid  = threadIdx.x;
    const int lane = tid & 31;
    const int warp = tid >> 5;
    const int gid  = lane >> 2;
    const int t4   = lane & 3;
    const int rg   = warp >> 2;           // row group: 32 rows each
    const int ch   = warp & 3;            // column quarter
    const int mbase = rg * 32;
    const int nbase = ch * 16;            // S cols per warp: 16
    const int dbase = ch * 32;            // O cols per warp: 32

    const uint32_t smb = (uint32_t)__cvta_generic_to_shared(sm);
    const float NEGINF = __int_as_float(0xff800000);

    const float* gQ  = g_Qs + ((size_t)head * S + q0) * DH;
    const float* gKh = g_Ks + (size_t)head * S * DH;
    const float* gVh = g_Vs + (size_t)head * S * DH;   // [T][d][64] packed

    const int w2 = 2 * t4;
    const int e0 = 2 * (w2 & 3) + (w2 >> 2);             // packed offset col c
    const int e1 = 2 * ((w2 + 1) & 3) + ((w2 + 1) >> 2); // packed offset col c+1

    // ---- Prologue: async load Q tile + KV tile 0 ----
    #pragma unroll
    for (int it = 0; it < 8; ++it){
        int i = it * NT + tid;                 // 2048 float4 (64x128)
        int row = i >> 5, c4 = (i & 31) << 2;
        cpa16(smb + (uint32_t)(F_Q + row * SROW + c4) * 4, gQ + row * DH + c4);
    }
    #pragma unroll
    for (int it = 0; it < 8; ++it){
        int i = it * NT + tid;
        int row = i >> 5, c4 = (i & 31) << 2;
        cpa16(smb + (uint32_t)(F_KP + row * SROW + c4) * 4, gKh + row * DH + c4);
    }
    #pragma unroll
    for (int it = 0; it < 8; ++it){
        int i = it * NT + tid;                 // 2048 float4 (128x64)
        int row = i >> 4, c4 = (i & 15) << 2;
        cpa16(smb + (uint32_t)(F_V + row * VSTR + c4) * 4, gVh + row * 64 + c4);
    }
    cpa_commit();

    float o[2][4][4];
    #pragma unroll
    for (int a = 0; a < 2; ++a)
        #pragma unroll
        for (int b = 0; b < 4; ++b)
            o[a][b][0] = o[a][b][1] = o[a][b][2] = o[a][b][3] = 0.f;
    float m[4] = {NEGINF, NEGINF, NEGINF, NEGINF};
    float l[4] = {0.f, 0.f, 0.f, 0.f};

    #pragma unroll 1
    for (int j = 0; j <= qt; ++j){
        cpa_wait0();
        __syncthreads();

        // ---- MMA1: S = Q * K^T  (32 rows x 16 cols per warp) ----
        float sa[2][2][4];
        #pragma unroll
        for (int a = 0; a < 2; ++a)
            #pragma unroll
            for (int b = 0; b < 2; ++b)
                sa[a][b][0] = sa[a][b][1] = sa[a][b][2] = sa[a][b][3] = 0.f;

        #pragma unroll
        for (int ks = 0; ks < 16; ++ks){
            int co = ks * 8 + w2;
            const float* qr = sm + F_Q + (mbase + gid) * SROW + co;
            float2 A02 = *(const float2*)(qr);
            float2 A13 = *(const float2*)(qr + 8*SROW);
            float2 A46 = *(const float2*)(qr + 16*SROW);
            float2 A57 = *(const float2*)(qr + 24*SROW);
            #pragma unroll
            for (int nt = 0; nt < 2; ++nt){
                float2 B = *(const float2*)(sm + F_KP + (nbase + nt*8 + gid) * SROW + co);
                mma_tf32(sa[0][nt], A02.x, A13.x, A02.y, A13.y, B.x, B.y);
                mma_tf32(sa[1][nt], A46.x, A57.x, A46.y, A57.y, B.x, B.y);
            }
        }

        // ---- Causal mask on diagonal tile ----
        if (j == qt){
            #pragma unroll
            for (int mg = 0; mg < 2; ++mg){
                int r0 = mbase + 16*mg + gid, r1 = r0 + 8;
                #pragma unroll
                for (int nt = 0; nt < 2; ++nt){
                    int c = nbase + nt*8 + w2;
                    if (c     > r0) sa[mg][nt][0] = NEGINF;
                    if (c + 1 > r0) sa[mg][nt][1] = NEGINF;
                    if (c     > r1) sa[mg][nt][2] = NEGINF;
                    if (c + 1 > r1) sa[mg][nt][3] = NEGINF;
                }
            }
        }

        // ---- Partial row max, exchange across 4 column-warps ----
        float mx[4] = {NEGINF, NEGINF, NEGINF, NEGINF};
        #pragma unroll
        for (int nt = 0; nt < 2; ++nt){
            mx[0] = fmaxf(mx[0], fmaxf(sa[0][nt][0], sa[0][nt][1]));
            mx[1] = fmaxf(mx[1], fmaxf(sa[0][nt][2], sa[0][nt][3]));
            mx[2] = fmaxf(mx[2], fmaxf(sa[1][nt][0], sa[1][nt][1]));
            mx[3] = fmaxf(mx[3], fmaxf(sa[1][nt][2], sa[1][nt][3]));
        }
        #pragma unroll
        for (int i = 0; i < 4; ++i){
            mx[i] = fmaxf(mx[i], __shfl_xor_sync(0xffffffffu, mx[i], 1));
            mx[i] = fmaxf(mx[i], __shfl_xor_sync(0xffffffffu, mx[i], 2));
        }
        if (t4 == 0){
            #pragma unroll
            for (int i = 0; i < 4; ++i)
                sm[F_X1 + (mbase + gid + 8*i)*4 + ch] = mx[i];
        }
        __syncthreads();   // X1 visible + all K reads done (P store safe)

        float mn[4], al[4];
        #pragma unroll
        for (int i = 0; i < 4; ++i){
            int b = F_X1 + (mbase + gid + 8*i)*4;
            float v = fmaxf(fmaxf(sm[b], sm[b+1]), fmaxf(sm[b+2], sm[b+3]));
            mn[i] = fmaxf(m[i], v);
            al[i] = ex2f(m[i] - mn[i]);
            m[i]  = mn[i];
        }

        // ---- P = exp2(S - m); store packed into K buffer; partial row sums ----
        float rs[4] = {0.f, 0.f, 0.f, 0.f};
        #pragma unroll
        for (int mg = 0; mg < 2; ++mg){
            #pragma unroll
            for (int nt = 0; nt < 2; ++nt){
                float p0 = ex2f(sa[mg][nt][0] - mn[2*mg]);
                float p1 = ex2f(sa[mg][nt][1] - mn[2*mg]);
                float p2 = ex2f(sa[mg][nt][2] - mn[2*mg+1]);
                float p3 = ex2f(sa[mg][nt][3] - mn[2*mg+1]);
                rs[2*mg]   += p0 + p1;
                rs[2*mg+1] += p2 + p3;
                int base8 = nbase + 8*nt;
                float* pr0 = sm + F_KP + (mbase + 16*mg + gid) * SROW + base8;
                float* pr1 = pr0 + 8 * SROW;
                pr0[e0] = p0;  pr0[e1] = p1;
                pr1[e0] = p2;  pr1[e1] = p3;
            }
        }
        #pragma unroll
        for (int i = 0; i < 4; ++i){
            rs[i] += __shfl_xor_sync(0xffffffffu, rs[i], 1);
            rs[i] += __shfl_xor_sync(0xffffffffu, rs[i], 2);
        }
        if (t4 == 0){
            #pragma unroll
            for (int i = 0; i < 4; ++i)
                sm[F_X2 + (mbase + gid + 8*i)*4 + ch] = rs[i];
        }
        asm volatile("bar.sync %0, 128;" :: "r"(1 + rg) : "memory");  // row-group barrier

        #pragma unroll
        for (int i = 0; i < 4; ++i){
            int b = F_X2 + (mbase + gid + 8*i)*4;
            l[i] = l[i]*al[i] + (sm[b] + sm[b+1] + sm[b+2] + sm[b+3]);
        }
        #pragma unroll
        for (int mg = 0; mg < 2; ++mg){
            #pragma unroll
            for (int nt = 0; nt < 4; ++nt){
                o[mg][nt][0] *= al[2*mg];   o[mg][nt][1] *= al[2*mg];
                o[mg][nt][2] *= al[2*mg+1]; o[mg][nt][3] *= al[2*mg+1];
            }
        }

        // ---- MMA2: O += P * V  (32 rows x 32 d-cols per warp, k=64) ----
        #pragma unroll
        for (int ks = 0; ks < 8; ++ks){
            int co = ks * 8 + w2;
            const float* pr = sm + F_KP + (mbase + gid) * SROW + co;
            float2 A02 = *(const float2*)(pr);
            float2 A13 = *(const float2*)(pr + 8*SROW);
            float2 A46 = *(const float2*)(pr + 16*SROW);
            float2 A57 = *(const float2*)(pr + 24*SROW);
            #pragma unroll
            for (int nt = 0; nt < 4; ++nt){
                float2 B = *(const float2*)(sm + F_V + (dbase + nt*8 + gid) * VSTR + co);
                mma_tf32(o[0][nt], A02.x, A13.x, A02.y, A13.y, B.x, B.y);
                mma_tf32(o[1][nt], A46.x, A57.x, A46.y, A57.y, B.x, B.y);
            }
        }

        __syncthreads();   // all reads of P (K buf) and V done
        if (j < qt){
            const float* gK = gKh + (size_t)(j + 1) * BN * DH;
            const float* gV = gVh + (size_t)(j + 1) * 128 * 64;
            #pragma unroll
            for (int it = 0; it < 8; ++it){
                int i = it * NT + tid;
                int row = i >> 5, c4 = (i & 31) << 2;
                cpa16(smb + (uint32_t)(F_KP + row * SROW + c4) * 4, gK + row * DH + c4);
            }
            #pragma unroll
            for (int it = 0; it < 8; ++it){
                int i = it * NT + tid;
                int row = i >> 4, c4 = (i & 15) << 2;
                cpa16(smb + (uint32_t)(F_V + row * VSTR + c4) * 4, gV + row * 64 + c4);
            }
            cpa_commit();
        }
    }

    // ---- Epilogue: O / l -> Out[(q0+row), head*128 + d] ----
    #pragma unroll
    for (int mg = 0; mg < 2; ++mg){
        int r0 = q0 + mbase + 16*mg + gid;
        float i0 = 1.0f / l[2*mg];
        float i1 = 1.0f / l[2*mg + 1];
        #pragma unroll
        for (int nt = 0; nt < 4; ++nt){
            int c = head * DH + dbase + nt*8 + w2;
            *(float2*)(Out + (size_t)r0 * DM + c) =
                make_float2(o[mg][nt][0] * i0, o[mg][nt][1] * i0);
            *(float2*)(Out + (size_t)(r0 + 8) * DM + c) =
                make_float2(o[mg][nt][2] * i1, o[mg][nt][3] * i1);
        }
    }
}

extern "C" void kernel_launch(void* const* d_in, const int* in_sizes, int n_in,
                              void* d_out, int out_size)
{
    (void)in_sizes; (void)n_in; (void)out_size;
    const float* q = (const float*)d_in[0];
    const float* k = (const float*)d_in[1];
    const float* v = (const float*)d_in[2];
    float* out = (float*)d_out;

    prep_qk<<<(H * S * 16) / 256, 256>>>(q, k);
    prep_v<<<H * 64 * 8, 128>>>(v);

    cudaFuncSetAttribute(fa_kernel,
                         cudaFuncAttributeMaxDynamicSharedMemorySize, SMEM_BYTES);
    dim3 grid(S / BM, H);
    fa_kernel<<<grid, NT, SMEM_BYTES>>>(out);
}

// round 7
// speedup vs baseline: 2.1434x; 2.1434x over previous
#include <cuda_runtime.h>
#include <cuda_fp16.h>
#include <cstdint>

#define H  16
#define S  4096
#define DH 128
#define DM 2048
#define BM 128
#define BN 64
#define NT 256            // 8 warps, each owns 16 Q rows x full KV width

// byte offsets in dynamic SMEM
#define QSTR  288         // bytes per Q row (128 halfs + 16 pad) : stride%128==32
#define KSTR  288
#define VSTR  160         // V row: 64 halfs + pad
#define B_Q   0
#define KSZ   (64*KSTR)   // 18432
#define VSZ   (128*VSTR)  // 20480
#define B_K0  (128*QSTR)          // 36864
#define B_K1  (B_K0 + KSZ)
#define B_V0  (B_K1 + KSZ)
#define B_V1  (B_V0 + VSZ)
#define SMEM_BYTES (B_V1 + VSZ)   // 114688 -> 2 CTAs/SM

// Prepass scratch: fp16, pair-permuted: each 16-elem block of the contiguous
// dim reordered in pairs (p0,p4,p1,p5,p2,p6,p3,p7) so fragment loads are LDS.64.
// g_Qh/g_Kh: [head][row][d(128)] (Q pre-scaled). g_Vh: [head][kvTile(64)][d(128)][kv(64)]
__device__ __align__(16) __half g_Qh[H*S*DH];
__device__ __align__(16) __half g_Kh[H*S*DH];
__device__ __align__(16) __half g_Vh[H*S*DH];

__device__ __forceinline__ float ex2f(float x){
    float r; asm("ex2.approx.ftz.f32 %0, %1;" : "=f"(r) : "f"(x)); return r;
}
__device__ __forceinline__ uint32_t packh2(float lo, float hi){
    uint32_t d; asm("cvt.rn.f16x2.f32 %0, %1, %2;" : "=r"(d) : "f"(hi), "f"(lo));
    return d;
}
__device__ __forceinline__ void mma16816(float c[4],
    uint32_t a0, uint32_t a1, uint32_t a2, uint32_t a3, uint32_t b0, uint32_t b1)
{
    asm volatile(
        "mma.sync.aligned.m16n8k16.row.col.f32.f16.f16.f32 "
        "{%0,%1,%2,%3}, {%4,%5,%6,%7}, {%8,%9}, {%0,%1,%2,%3};\n"
        : "+f"(c[0]), "+f"(c[1]), "+f"(c[2]), "+f"(c[3])
        : "r"(a0), "r"(a1), "r"(a2), "r"(a3), "r"(b0), "r"(b1));
}
__device__ __forceinline__ void cpa16(uint32_t dst, const void* src){
    asm volatile("cp.async.cg.shared.global [%0], [%1], 16;" :: "r"(dst), "l"(src));
}
__device__ __forceinline__ void cpa_commit(){
    asm volatile("cp.async.commit_group;" ::: "memory");
}
__device__ __forceinline__ void cpa_wait0(){
    asm volatile("cp.async.wait_group 0;" ::: "memory");
}

// ---- Prepass 1: Q,K -> fp16, pair-permuted d blocks (Q pre-scaled) ----
__global__ void prep_qk(const float* __restrict__ Q, const float* __restrict__ K)
{
    const float SC = 0.088388347648318447f * 1.4426950408889634f; // 1/sqrt(128)*log2e
    size_t base = ((size_t)blockIdx.x * blockDim.x + threadIdx.x) * 16;
    {
        const float4* q = (const float4*)(Q + base);
        float4 x0=q[0], x1=q[1], x2=q[2], x3=q[3];
        __half2 h[8];
        h[0]=__floats2half2_rn(x0.x*SC,x0.y*SC); h[1]=__floats2half2_rn(x2.x*SC,x2.y*SC);
        h[2]=__floats2half2_rn(x0.z*SC,x0.w*SC); h[3]=__floats2half2_rn(x2.z*SC,x2.w*SC);
        h[4]=__floats2half2_rn(x1.x*SC,x1.y*SC); h[5]=__floats2half2_rn(x3.x*SC,x3.y*SC);
        h[6]=__floats2half2_rn(x1.z*SC,x1.w*SC); h[7]=__floats2half2_rn(x3.z*SC,x3.w*SC);
        *(float4*)(g_Qh+base)   = *(float4*)(h);
        *(float4*)(g_Qh+base+8) = *(float4*)(h+4);
    }
    {
        const float4* k = (const float4*)(K + base);
        float4 x0=k[0], x1=k[1], x2=k[2], x3=k[3];
        __half2 h[8];
        h[0]=__floats2half2_rn(x0.x,x0.y); h[1]=__floats2half2_rn(x2.x,x2.y);
        h[2]=__floats2half2_rn(x0.z,x0.w); h[3]=__floats2half2_rn(x2.z,x2.w);
        h[4]=__floats2half2_rn(x1.x,x1.y); h[5]=__floats2half2_rn(x3.x,x3.y);
        h[6]=__floats2half2_rn(x1.z,x1.w); h[7]=__floats2half2_rn(x3.z,x3.w);
        *(float4*)(g_Kh+base)   = *(float4*)(h);
        *(float4*)(g_Kh+base+8) = *(float4*)(h+4);
    }
}

// ---- Prepass 2: V -> fp16 transposed [d][kv] per 64-kv tile, kv-pair permuted ----
__global__ void prep_v(const float* __restrict__ V)
{
    int b    = blockIdx.x;          // 16*64*4
    int kb   = b & 3;
    int T    = (b >> 2) & 63;
    int head = b >> 8;
    int d    = threadIdx.x;         // 128
    int kv0  = T * 64 + kb * 16;
    const float* src = V + ((size_t)head * S + kv0) * DH + d;
    float x[16];
    #pragma unroll
    for (int w = 0; w < 16; ++w) x[w] = src[(size_t)w * DH];
    __half2 h[8];
    h[0]=__floats2half2_rn(x[0],x[1]);   h[1]=__floats2half2_rn(x[8],x[9]);
    h[2]=__floats2half2_rn(x[2],x[3]);   h[3]=__floats2half2_rn(x[10],x[11]);
    h[4]=__floats2half2_rn(x[4],x[5]);   h[5]=__floats2half2_rn(x[12],x[13]);
    h[6]=__floats2half2_rn(x[6],x[7]);   h[7]=__floats2half2_rn(x[14],x[15]);
    __half* dst = g_Vh + (((size_t)head*64 + T)*128 + d)*64 + kb*16;
    *(float4*)(dst)   = *(float4*)(h);
    *(float4*)(dst+8) = *(float4*)(h+4);
}

// ---------------- Main flash-attention kernel ----------------
extern __shared__ char smc[];

__global__ __launch_bounds__(NT, 2)
void fa_kernel(float* __restrict__ Out)
{
    const int qt   = (int)gridDim.x - 1 - (int)blockIdx.x;  // heavy tiles first
    const int head = blockIdx.y;
    const int q0   = qt * BM;
    const int tid  = threadIdx.x;
    const int lane = tid & 31;
    const int warp = tid >> 5;
    const int gid  = lane >> 2;
    const int t4   = lane & 3;
    const int mbase = warp * 16;       // this warp's 16 rows

    const uint32_t smb = (uint32_t)__cvta_generic_to_shared(smc);
    const float NEGINF = __int_as_float(0xff800000);
    const int jmax = 2*qt + 2;

    const char* gQ = (const char*)(g_Qh + ((size_t)head*S + q0) * DH);
    const char* gK = (const char*)(g_Kh + (size_t)head*S*DH);
    const char* gV = (const char*)(g_Vh + (size_t)head*S*DH);

    // ---- Prologue: Q tile + K/V tile 0 ----
    #pragma unroll
    for (int it = 0; it < 8; ++it){
        int i = it*NT + tid; int r = i >> 4, c = (i & 15) * 16;
        cpa16(smb + B_Q + r*QSTR + c, gQ + r*256 + c);
    }
    #pragma unroll
    for (int it = 0; it < 4; ++it){
        int i = it*NT + tid; int r = i >> 4, c = (i & 15) * 16;
        cpa16(smb + B_K0 + r*KSTR + c, gK + r*256 + c);
    }
    #pragma unroll
    for (int it = 0; it < 4; ++it){
        int i = it*NT + tid; int r = i >> 3, c = (i & 7) * 16;
        cpa16(smb + B_V0 + r*VSTR + c, gV + r*128 + c);
    }
    cpa_commit();

    float o[16][4];
    #pragma unroll
    for (int nt = 0; nt < 16; ++nt)
        o[nt][0] = o[nt][1] = o[nt][2] = o[nt][3] = 0.f;
    float m0 = NEGINF, m1 = NEGINF, l0 = 0.f, l1 = 0.f;

    #pragma unroll 1
    for (int j = 0; j < jmax; ++j){
        cpa_wait0();
        __syncthreads();                      // data visible + prev tile fully consumed

        if (j + 1 < jmax){                    // prefetch next tile into alt buffers
            const char* sK = gK + (size_t)(j+1) * 16384;
            const char* sV = gV + (size_t)(j+1) * 16384;
            uint32_t dK = smb + ((j & 1) ? B_K0 : B_K1);
            uint32_t dV = smb + ((j & 1) ? B_V0 : B_V1);
            #pragma unroll
            for (int it = 0; it < 4; ++it){
                int i = it*NT + tid; int r = i >> 4, c = (i & 15) * 16;
                cpa16(dK + r*KSTR + c, sK + r*256 + c);
            }
            #pragma unroll
            for (int it = 0; it < 4; ++it){
                int i = it*NT + tid; int r = i >> 3, c = (i & 7) * 16;
                cpa16(dV + r*VSTR + c, sV + r*128 + c);
            }
            cpa_commit();
        }

        if (j * BN <= q0 + mbase + 15){       // warp has unmasked work in this tile
            const char* qp = smc + B_Q + (mbase + gid)*QSTR + t4*8;
            const char* kp = smc + ((j & 1) ? B_K1 : B_K0) + gid*KSTR + t4*8;

            // ---- MMA1: S = Q K^T  (16 rows x 64 cols, k=128) ----
            float s[8][4];
            #pragma unroll
            for (int nt = 0; nt < 8; ++nt)
                s[nt][0] = s[nt][1] = s[nt][2] = s[nt][3] = 0.f;
            #pragma unroll
            for (int ks = 0; ks < 8; ++ks){
                uint2 A02 = *(const uint2*)(qp + ks*32);
                uint2 A13 = *(const uint2*)(qp + 8*QSTR + ks*32);
                #pragma unroll
                for (int nt = 0; nt < 8; ++nt){
                    uint2 B = *(const uint2*)(kp + nt*8*KSTR + ks*32);
                    mma16816(s[nt], A02.x, A13.x, A02.y, A13.y, B.x, B.y);
                }
            }

            // ---- Causal mask (tiles overlapping the diagonal) ----
            if ((j + 1) * BN > q0 + mbase){
                int r0 = q0 + mbase + gid, r1 = r0 + 8;
                int cb = j * BN + 2*t4;
                #pragma unroll
                for (int nt = 0; nt < 8; ++nt){
                    int c = cb + nt*8;
                    if (c     > r0) s[nt][0] = NEGINF;
                    if (c + 1 > r0) s[nt][1] = NEGINF;
                    if (c     > r1) s[nt][2] = NEGINF;
                    if (c + 1 > r1) s[nt][3] = NEGINF;
                }
            }

            // ---- Warp-local online softmax ----
            float mx0 = NEGINF, mx1 = NEGINF;
            #pragma unroll
            for (int nt = 0; nt < 8; ++nt){
                mx0 = fmaxf(mx0, fmaxf(s[nt][0], s[nt][1]));
                mx1 = fmaxf(mx1, fmaxf(s[nt][2], s[nt][3]));
            }
            mx0 = fmaxf(mx0, __shfl_xor_sync(0xffffffffu, mx0, 1));
            mx0 = fmaxf(mx0, __shfl_xor_sync(0xffffffffu, mx0, 2));
            mx1 = fmaxf(mx1, __shfl_xor_sync(0xffffffffu, mx1, 1));
            mx1 = fmaxf(mx1, __shfl_xor_sync(0xffffffffu, mx1, 2));
            float n0 = fmaxf(m0, mx0), n1 = fmaxf(m1, mx1);
            float al0 = ex2f(m0 - n0), al1 = ex2f(m1 - n1);
            m0 = n0; m1 = n1;

            uint32_t P[16];
            float rs0 = 0.f, rs1 = 0.f;
            #pragma unroll
            for (int nt = 0; nt < 8; ++nt){
                float p0 = ex2f(s[nt][0] - m0), p1 = ex2f(s[nt][1] - m0);
                float p2 = ex2f(s[nt][2] - m1), p3 = ex2f(s[nt][3] - m1);
                rs0 += p0 + p1;  rs1 += p2 + p3;
                int ks = nt >> 1, hh = nt & 1;
                P[ks*4 + hh*2 + 0] = packh2(p0, p1);   // A-frag rows gid
                P[ks*4 + hh*2 + 1] = packh2(p2, p3);   // A-frag rows gid+8
            }
            rs0 += __shfl_xor_sync(0xffffffffu, rs0, 1);
            rs0 += __shfl_xor_sync(0xffffffffu, rs0, 2);
            rs1 += __shfl_xor_sync(0xffffffffu, rs1, 1);
            rs1 += __shfl_xor_sync(0xffffffffu, rs1, 2);
            l0 = l0*al0 + rs0;
            l1 = l1*al1 + rs1;

            #pragma unroll
            for (int nt = 0; nt < 16; ++nt){
                o[nt][0] *= al0; o[nt][1] *= al0;
                o[nt][2] *= al1; o[nt][3] *= al1;
            }

            // ---- MMA2: O += P V  (P in registers, k=64) ----
            const char* vp = smc + ((j & 1) ? B_V1 : B_V0) + gid*VSTR + t4*8;
            #pragma unroll
            for (int ks = 0; ks < 4; ++ks){
                uint32_t a0 = P[ks*4], a1 = P[ks*4+1], a2 = P[ks*4+2], a3 = P[ks*4+3];
                #pragma unroll
                for (int nt = 0; nt < 16; ++nt){
                    uint2 B = *(const uint2*)(vp + nt*8*VSTR + ks*32);
                    mma16816(o[nt], a0, a1, a2, a3, B.x, B.y);
                }
            }
        }
    }

    // ---- Epilogue: O / l -> Out[(q0+row), head*128 + d] ----
    float i0 = 1.0f / l0, i1 = 1.0f / l1;
    float* po = Out + (size_t)(q0 + mbase + gid) * DM + head * DH + 2*t4;
    #pragma unroll
    for (int nt = 0; nt < 16; ++nt){
        *(float2*)(po + nt*8)          = make_float2(o[nt][0]*i0, o[nt][1]*i0);
        *(float2*)(po + 8*DM + nt*8)   = make_float2(o[nt][2]*i1, o[nt][3]*i1);
    }
}

extern "C" void kernel_launch(void* const* d_in, const int* in_sizes, int n_in,
                              void* d_out, int out_size)
{
    (void)in_sizes; (void)n_in; (void)out_size;
    const float* q = (const float*)d_in[0];
    const float* k = (const float*)d_in[1];
    const float* v = (const float*)d_in[2];
    float* out = (float*)d_out;

    prep_qk<<<(H*S*DH/16)/256, 256>>>(q, k);
    prep_v<<<H * 64 * 4, 128>>>(v);

    cudaFuncSetAttribute(fa_kernel,
                         cudaFuncAttributeMaxDynamicSharedMemorySize, SMEM_BYTES);
    dim3 grid(S / BM, H);
    fa_kernel<<<grid, NT, SMEM_BYTES>>>(out);
}